// round 4
// baseline (speedup 1.0000x reference)
#include <cuda_runtime.h>
#include <math.h>

#define NN 8192
#define CHID 256
#define CACT 128

// ---------------- scratch (no allocations allowed) ----------------
__device__ float g_X [NN * 32];
__device__ float g_S1[NN * CHID];
__device__ float g_G1[NN * CHID];
__device__ float g_S2[NN * CACT];
__device__ float g_G2[NN * CACT];
__device__ float g_Z1[NN * CACT];
__device__ float g_Z2[NN * CACT];
__device__ float g_rs11[NN], g_rs22[NN], g_rs12[NN], g_cs12[NN];
__device__ float g_d11[NN], g_d22[NN], g_d12[NN];

// ---------------- MLP: x = relu(feat@w1+b1)@w2+b2  (512->64->32), 4 rows/block ----------------
__global__ void k_mlp(const float* __restrict__ feat,
                      const float* __restrict__ w1, const float* __restrict__ b1,
                      const float* __restrict__ w2, const float* __restrict__ b2,
                      float* __restrict__ xout)
{
    __shared__ float sf[4 * 512];
    __shared__ float t1[4][64];
    int tid = threadIdx.x;           // 64 threads
    int r0 = blockIdx.x * 4;
    const float4* f4 = (const float4*)(feat + (size_t)r0 * 512);
    #pragma unroll
    for (int i = 0; i < 8; i++)
        ((float4*)sf)[tid + i * 64] = f4[tid + i * 64];
    __syncthreads();
    float a0 = b1[tid], a1 = a0, a2 = a0, a3 = a0;
    #pragma unroll 4
    for (int k = 0; k < 512; k++) {
        float wv = w1[k * 64 + tid];
        a0 = fmaf(sf[k], wv, a0);
        a1 = fmaf(sf[512 + k], wv, a1);
        a2 = fmaf(sf[1024 + k], wv, a2);
        a3 = fmaf(sf[1536 + k], wv, a3);
    }
    t1[0][tid] = fmaxf(a0, 0.f); t1[1][tid] = fmaxf(a1, 0.f);
    t1[2][tid] = fmaxf(a2, 0.f); t1[3][tid] = fmaxf(a3, 0.f);
    __syncthreads();
    #pragma unroll
    for (int t = tid; t < 128; t += 64) {
        int r = t >> 5, o = t & 31;
        float acc = b2[o];
        #pragma unroll
        for (int k = 0; k < 64; k++)
            acc = fmaf(t1[r][k], w2[k * 32 + o], acc);
        xout[(r0 + r) * 32 + o] = acc;
    }
}

// ---------------- support1 = x @ w_g1  (32 -> 256), one row/block ----------------
__global__ void k_sup1(const float* __restrict__ x, const float* __restrict__ w,
                       float* __restrict__ sup)
{
    __shared__ float sx[32];
    int tid = threadIdx.x;           // 256
    int row = blockIdx.x;
    if (tid < 32) sx[tid] = x[row * 32 + tid];
    __syncthreads();
    float acc = 0.f;
    #pragma unroll
    for (int k = 0; k < 32; k++)
        acc = fmaf(sx[k], w[k * 256 + tid], acc);
    sup[row * 256 + tid] = acc;
}

// ---------------- init accumulator to broadcast bias ----------------
__global__ void k_binit(float* __restrict__ acc, const float* __restrict__ b,
                        int cmask, int total)
{
    int i = blockIdx.x * blockDim.x + threadIdx.x;
    if (i < total) acc[i] = b[i & cmask];
}

// ---------------- edge scatter: acc[dst] += w * sup[src]  (warp per edge) ----------------
__global__ void k_scatter(const int* __restrict__ ei, const float* __restrict__ ew,
                          const float* __restrict__ sup, float* __restrict__ acc,
                          int E, int C)
{
    int gw = (blockIdx.x * blockDim.x + threadIdx.x) >> 5;
    int lane = threadIdx.x & 31;
    if (gw >= E) return;
    int dst = ei[gw];
    int src = ei[E + gw];
    float w = ew[gw];
    const float4* s4 = (const float4*)(sup + (size_t)src * C);
    float* a = acc + (size_t)dst * C;
    int n4 = C >> 2;
    for (int j = lane; j < n4; j += 32) {
        float4 v = s4[j];
        atomicAdd(a + 4 * j + 0, v.x * w);
        atomicAdd(a + 4 * j + 1, v.y * w);
        atomicAdd(a + 4 * j + 2, v.z * w);
        atomicAdd(a + 4 * j + 3, v.w * w);
    }
}

// ---------------- support2 = relu(h) @ w_g2  (256 -> 128), 4 rows/block ----------------
__global__ void k_sup2(const float* __restrict__ h, const float* __restrict__ w,
                       float* __restrict__ sup)
{
    __shared__ float sh[4 * 256];
    int tid = threadIdx.x;           // 128
    int r0 = blockIdx.x * 4;
    #pragma unroll
    for (int i = tid; i < 1024; i += 128)
        sh[i] = fmaxf(h[(size_t)r0 * 256 + i], 0.f);
    __syncthreads();
    float a0 = 0, a1 = 0, a2 = 0, a3 = 0;
    #pragma unroll 4
    for (int k = 0; k < 256; k++) {
        float wv = w[k * 128 + tid];
        a0 = fmaf(sh[k], wv, a0);
        a1 = fmaf(sh[256 + k], wv, a1);
        a2 = fmaf(sh[512 + k], wv, a2);
        a3 = fmaf(sh[768 + k], wv, a3);
    }
    sup[(r0 + 0) * 128 + tid] = a0;
    sup[(r0 + 1) * 128 + tid] = a1;
    sup[(r0 + 2) * 128 + tid] = a2;
    sup[(r0 + 3) * 128 + tid] = a3;
}

// ---------------- proj + L2 normalize: z = norm(elu(h@w1+b1)@w2+b2) ----------------
__global__ void k_proj(const float* __restrict__ h,
                       const float* __restrict__ w1, const float* __restrict__ b1,
                       const float* __restrict__ w2, const float* __restrict__ b2,
                       float* __restrict__ z)
{
    __shared__ float sh[128];
    __shared__ float t[64];
    __shared__ float red[128];
    int tid = threadIdx.x;           // 128
    int row = blockIdx.x;
    sh[tid] = h[row * 128 + tid];
    __syncthreads();
    if (tid < 64) {
        float a = b1[tid];
        #pragma unroll
        for (int k = 0; k < 128; k++)
            a = fmaf(sh[k], w1[k * 64 + tid], a);
        t[tid] = a > 0.f ? a : expm1f(a);
    }
    __syncthreads();
    float a = b2[tid];
    #pragma unroll
    for (int k = 0; k < 64; k++)
        a = fmaf(t[k], w2[k * 128 + tid], a);
    red[tid] = a * a;
    __syncthreads();
    for (int st = 64; st; st >>= 1) {
        if (tid < st) red[tid] += red[tid + st];
        __syncthreads();
    }
    float inv = 1.f / fmaxf(sqrtf(red[0]), 1e-12f);
    z[row * 128 + tid] = a * inv;
}

// ---------------- zero the 4 rowsum accumulators ----------------
__global__ void k_zero4(float* a, float* b, float* c, float* d)
{
    int i = blockIdx.x * blockDim.x + threadIdx.x;
    if (i < NN) { a[i] = 0.f; b[i] = 0.f; c[i] = 0.f; d[i] = 0.f; }
}

// ---------------- pairwise exp-sum tiles ----------------
// job 0: S11 = Z1 Z1^T (symmetric, only tj>=ti; off-diag tile feeds both row sums)
// job 1: S22 = Z2 Z2^T (same)
// job 2: S12 = Z1 Z2^T (full; row sums -> rs12, col sums -> cs12, diag -> d12)
// 64x64 tile, K=128 in two 64-chunks, 256 threads, 4x4 microtile/thread.
__global__ void k_pair(const float* __restrict__ Z1, const float* __restrict__ Z2,
                       float* __restrict__ rs11, float* __restrict__ d11,
                       float* __restrict__ rs22, float* __restrict__ d22,
                       float* __restrict__ rs12, float* __restrict__ cs12,
                       float* __restrict__ d12)
{
    int job = blockIdx.z;
    int ti = blockIdx.y, tj = blockIdx.x;
    bool sym = (job < 2);
    if (sym && tj < ti) return;
    const float* A = (job == 1) ? Z2 : Z1;
    const float* B = (job == 0) ? Z1 : Z2;

    __shared__ __align__(16) float As[64][64];   // [k][i]
    __shared__ __align__(16) float Bs[64][64];   // [k][j]
    __shared__ float rs[64], cs[64];

    int tid = threadIdx.x;           // 256
    int tx = tid & 15, ty = tid >> 4;

    float acc[4][4];
    #pragma unroll
    for (int r = 0; r < 4; r++)
        #pragma unroll
        for (int c = 0; c < 4; c++) acc[r][c] = 0.f;

    if (tid < 64) { rs[tid] = 0.f; cs[tid] = 0.f; }

    for (int kc = 0; kc < 2; kc++) {
        __syncthreads();
        #pragma unroll
        for (int m = 0; m < 4; m++) {
            int idx = m * 256 + tid;
            int i = idx & 63, k4 = idx >> 6;
            float4 va = *(const float4*)(A + (size_t)(ti * 64 + i) * 128 + kc * 64 + k4 * 4);
            As[k4 * 4 + 0][i] = va.x; As[k4 * 4 + 1][i] = va.y;
            As[k4 * 4 + 2][i] = va.z; As[k4 * 4 + 3][i] = va.w;
            float4 vb = *(const float4*)(B + (size_t)(tj * 64 + i) * 128 + kc * 64 + k4 * 4);
            Bs[k4 * 4 + 0][i] = vb.x; Bs[k4 * 4 + 1][i] = vb.y;
            Bs[k4 * 4 + 2][i] = vb.z; Bs[k4 * 4 + 3][i] = vb.w;
        }
        __syncthreads();
        #pragma unroll
        for (int kk = 0; kk < 64; kk++) {
            float4 a4 = *(const float4*)&As[kk][ty * 4];
            float4 b4 = *(const float4*)&Bs[kk][tx * 4];
            float av[4] = {a4.x, a4.y, a4.z, a4.w};
            float bv[4] = {b4.x, b4.y, b4.z, b4.w};
            #pragma unroll
            for (int r = 0; r < 4; r++)
                #pragma unroll
                for (int c = 0; c < 4; c++)
                    acc[r][c] = fmaf(av[r], bv[c], acc[r][c]);
        }
    }
    __syncthreads();

    float* D = (job == 0) ? d11 : (job == 1) ? d22 : d12;
    bool dtile = (ti == tj);
    float rpart[4] = {0, 0, 0, 0};
    float cpart[4] = {0, 0, 0, 0};
    #pragma unroll
    for (int r = 0; r < 4; r++) {
        #pragma unroll
        for (int c = 0; c < 4; c++) {
            float e = __expf(acc[r][c] * 2.0f);   // 1/TEMP = 2
            rpart[r] += e;
            cpart[c] += e;
            if (dtile && (ty * 4 + r) == (tx * 4 + c))
                D[ti * 64 + ty * 4 + r] = e;
        }
    }
    #pragma unroll
    for (int r = 0; r < 4; r++) atomicAdd(&rs[ty * 4 + r], rpart[r]);
    #pragma unroll
    for (int c = 0; c < 4; c++) atomicAdd(&cs[tx * 4 + c], cpart[c]);
    __syncthreads();

    if (tid < 64) {
        if (job == 0) {
            atomicAdd(&rs11[ti * 64 + tid], rs[tid]);
            if (tj > ti) atomicAdd(&rs11[tj * 64 + tid], cs[tid]);
        } else if (job == 1) {
            atomicAdd(&rs22[ti * 64 + tid], rs[tid]);
            if (tj > ti) atomicAdd(&rs22[tj * 64 + tid], cs[tid]);
        } else {
            atomicAdd(&rs12[ti * 64 + tid], rs[tid]);
            atomicAdd(&cs12[tj * 64 + tid], cs[tid]);
        }
    }
}

// ---------------- final loss reduction ----------------
__global__ void k_loss(const float* __restrict__ rs11, const float* __restrict__ d11,
                       const float* __restrict__ rs22, const float* __restrict__ d22,
                       const float* __restrict__ rs12, const float* __restrict__ cs12,
                       const float* __restrict__ d12, float* __restrict__ out)
{
    __shared__ float red[256];
    int tid = threadIdx.x;
    float s = 0.f;
    for (int i = tid; i < NN; i += 256) {
        float ld = logf(d12[i]);
        float l1 = logf(rs11[i] + rs12[i] - d11[i]) - ld;
        float l2 = logf(rs22[i] + cs12[i] - d22[i]) - ld;
        s += 0.5f * (l1 + l2);
    }
    red[tid] = s;
    __syncthreads();
    for (int st = 128; st; st >>= 1) {
        if (tid < st) red[tid] += red[tid + st];
        __syncthreads();
    }
    if (tid == 0) out[0] = red[0] / (float)NN;
}

// ---------------- launch ----------------
extern "C" void kernel_launch(void* const* d_in, const int* in_sizes, int n_in,
                              void* d_out, int out_size)
{
    const float* feat[2] = {(const float*)d_in[0], (const float*)d_in[1]};
    const int*   ei[2]   = {(const int*)d_in[2], (const int*)d_in[4]};
    const float* ew[2]   = {(const float*)d_in[3], (const float*)d_in[5]};
    const float* w_l1a = (const float*)d_in[6];
    const float* b_l1a = (const float*)d_in[7];
    const float* w_l1b = (const float*)d_in[8];
    const float* b_l1b = (const float*)d_in[9];
    const float* w_g1  = (const float*)d_in[10];
    const float* b_g1  = (const float*)d_in[11];
    const float* w_g2  = (const float*)d_in[12];
    const float* b_g2  = (const float*)d_in[13];
    const float* w_fc1 = (const float*)d_in[14];
    const float* b_fc1 = (const float*)d_in[15];
    const float* w_fc2 = (const float*)d_in[16];
    const float* b_fc2 = (const float*)d_in[17];
    int E = in_sizes[3];

    float *X, *S1, *G1, *S2, *G2, *Z1, *Z2;
    float *rs11, *rs22, *rs12, *cs12, *d11, *d22, *d12;
    cudaGetSymbolAddress((void**)&X,  g_X);
    cudaGetSymbolAddress((void**)&S1, g_S1);
    cudaGetSymbolAddress((void**)&G1, g_G1);
    cudaGetSymbolAddress((void**)&S2, g_S2);
    cudaGetSymbolAddress((void**)&G2, g_G2);
    cudaGetSymbolAddress((void**)&Z1, g_Z1);
    cudaGetSymbolAddress((void**)&Z2, g_Z2);
    cudaGetSymbolAddress((void**)&rs11, g_rs11);
    cudaGetSymbolAddress((void**)&rs22, g_rs22);
    cudaGetSymbolAddress((void**)&rs12, g_rs12);
    cudaGetSymbolAddress((void**)&cs12, g_cs12);
    cudaGetSymbolAddress((void**)&d11, g_d11);
    cudaGetSymbolAddress((void**)&d22, g_d22);
    cudaGetSymbolAddress((void**)&d12, g_d12);

    int sgrid = (E + 7) / 8;   // 8 warps/block, 1 warp/edge

    for (int v = 0; v < 2; v++) {
        float* Zv = v ? Z2 : Z1;
        k_mlp   <<<NN / 4, 64>>>(feat[v], w_l1a, b_l1a, w_l1b, b_l1b, X);
        k_sup1  <<<NN, 256>>>(X, w_g1, S1);
        k_binit <<<NN * CHID / 256, 256>>>(G1, b_g1, CHID - 1, NN * CHID);
        k_scatter<<<sgrid, 256>>>(ei[v], ew[v], S1, G1, E, CHID);
        k_sup2  <<<NN / 4, 128>>>(G1, w_g2, S2);
        k_binit <<<NN * CACT / 256, 256>>>(G2, b_g2, CACT - 1, NN * CACT);
        k_scatter<<<sgrid, 256>>>(ei[v], ew[v], S2, G2, E, CACT);
        k_proj  <<<NN, 128>>>(G2, w_fc1, b_fc1, w_fc2, b_fc2, Zv);
    }

    k_zero4<<<NN / 256, 256>>>(rs11, rs22, rs12, cs12);
    dim3 gp(128, 128, 3);
    k_pair<<<gp, 256>>>(Z1, Z2, rs11, d11, rs22, d22, rs12, cs12, d12);
    k_loss<<<1, 256>>>(rs11, d11, rs22, d22, rs12, cs12, d12, (float*)d_out);
}

// round 9
// speedup vs baseline: 3.4328x; 3.4328x over previous
#include <cuda_runtime.h>
#include <cuda_bf16.h>
#include <math.h>
#include <stdint.h>

#define NN 8192
#define CHID 256
#define CACT 128
#define EMAX 262144

// ---------------- scratch (no allocations allowed) ----------------
__device__ float g_X [NN * 32];
__device__ float g_S1[NN * CHID];
__device__ float g_G1[NN * CHID];
__device__ float g_S2[NN * CACT];
__device__ float g_G2[NN * CACT];
__device__ __align__(16) __nv_bfloat16 g_Zb1[NN * CACT];
__device__ __align__(16) __nv_bfloat16 g_Zb2[NN * CACT];
__device__ float g_rs11[NN], g_rs22[NN], g_rs12[NN], g_cs12[NN];
__device__ float g_d11[NN], g_d22[NN], g_d12[NN];
__device__ int g_cnt[NN];
__device__ int g_cur[NN];
__device__ int g_rowstart[2 * (NN + 1)];
__device__ int g_eidx[2 * EMAX];

// ================= warp-MMA helpers (sm_80+ PTX, safe for compute_103) =================
__device__ __forceinline__ uint32_t smem_u32(const void* p) {
    uint32_t a;
    asm("{ .reg .u64 t; cvta.to.shared.u64 t, %1; cvt.u32.u64 %0, t; }" : "=r"(a) : "l"(p));
    return a;
}
__device__ __forceinline__ void ldsm_x4(uint32_t& r0, uint32_t& r1, uint32_t& r2, uint32_t& r3,
                                        uint32_t saddr) {
    asm volatile("ldmatrix.sync.aligned.m8n8.x4.shared.b16 {%0,%1,%2,%3}, [%4];"
                 : "=r"(r0), "=r"(r1), "=r"(r2), "=r"(r3) : "r"(saddr));
}
__device__ __forceinline__ void mma16816(float* c, uint32_t a0, uint32_t a1, uint32_t a2,
                                         uint32_t a3, uint32_t b0, uint32_t b1) {
    asm volatile(
        "mma.sync.aligned.m16n8k16.row.col.f32.bf16.bf16.f32 "
        "{%0,%1,%2,%3}, {%4,%5,%6,%7}, {%8,%9}, {%0,%1,%2,%3};"
        : "+f"(c[0]), "+f"(c[1]), "+f"(c[2]), "+f"(c[3])
        : "r"(a0), "r"(a1), "r"(a2), "r"(a3), "r"(b0), "r"(b1));
}

// ---------------- MLP: x = relu(feat@w1+b1)@w2+b2  (512->64->32), 4 rows/block ----------------
__global__ void k_mlp(const float* __restrict__ feat,
                      const float* __restrict__ w1, const float* __restrict__ b1,
                      const float* __restrict__ w2, const float* __restrict__ b2,
                      float* __restrict__ xout)
{
    __shared__ float sf[4 * 512];
    __shared__ float t1[4][64];
    int tid = threadIdx.x;           // 64 threads
    int r0 = blockIdx.x * 4;
    const float4* f4 = (const float4*)(feat + (size_t)r0 * 512);
    #pragma unroll
    for (int i = 0; i < 8; i++)
        ((float4*)sf)[tid + i * 64] = f4[tid + i * 64];
    __syncthreads();
    float a0 = b1[tid], a1 = a0, a2 = a0, a3 = a0;
    #pragma unroll 4
    for (int k = 0; k < 512; k++) {
        float wv = w1[k * 64 + tid];
        a0 = fmaf(sf[k], wv, a0);
        a1 = fmaf(sf[512 + k], wv, a1);
        a2 = fmaf(sf[1024 + k], wv, a2);
        a3 = fmaf(sf[1536 + k], wv, a3);
    }
    t1[0][tid] = fmaxf(a0, 0.f); t1[1][tid] = fmaxf(a1, 0.f);
    t1[2][tid] = fmaxf(a2, 0.f); t1[3][tid] = fmaxf(a3, 0.f);
    __syncthreads();
    #pragma unroll
    for (int t = tid; t < 128; t += 64) {
        int r = t >> 5, o = t & 31;
        float acc = b2[o];
        #pragma unroll
        for (int k = 0; k < 64; k++)
            acc = fmaf(t1[r][k], w2[k * 32 + o], acc);
        xout[(r0 + r) * 32 + o] = acc;
    }
}

// ---------------- support1 = x @ w_g1  (32 -> 256), one row/block ----------------
__global__ void k_sup1(const float* __restrict__ x, const float* __restrict__ w,
                       float* __restrict__ sup)
{
    __shared__ float sx[32];
    int tid = threadIdx.x;           // 256
    int row = blockIdx.x;
    if (tid < 32) sx[tid] = x[row * 32 + tid];
    __syncthreads();
    float acc = 0.f;
    #pragma unroll
    for (int k = 0; k < 32; k++)
        acc = fmaf(sx[k], w[k * 256 + tid], acc);
    sup[row * 256 + tid] = acc;
}

// ---------------- CSR build ----------------
__global__ void k_zcnt(int* __restrict__ cnt)
{
    int i = blockIdx.x * blockDim.x + threadIdx.x;
    if (i < NN) cnt[i] = 0;
}
__global__ void k_hist(const int* __restrict__ ei, int* __restrict__ cnt, int E)
{
    int e = blockIdx.x * blockDim.x + threadIdx.x;
    if (e < E) atomicAdd(&cnt[ei[e]], 1);
}
__global__ void k_scan(const int* __restrict__ cnt, int* __restrict__ rowstart,
                       int* __restrict__ cur)
{
    __shared__ int ps[1024];
    int t = threadIdx.x;             // 1024 threads
    int loc[8]; int s = 0;
    #pragma unroll
    for (int j = 0; j < 8; j++) { loc[j] = s; s += cnt[t * 8 + j]; }
    ps[t] = s;
    __syncthreads();
    for (int off = 1; off < 1024; off <<= 1) {
        int v = (t >= off) ? ps[t - off] : 0;
        __syncthreads();
        ps[t] += v;
        __syncthreads();
    }
    int b = ps[t] - s;               // exclusive base
    #pragma unroll
    for (int j = 0; j < 8; j++) { rowstart[t * 8 + j] = b + loc[j]; cur[t * 8 + j] = b + loc[j]; }
    if (t == 1023) rowstart[NN] = ps[1023];
}
__global__ void k_fill(const int* __restrict__ ei, int* __restrict__ cur,
                       int* __restrict__ eidx, int E)
{
    int e = blockIdx.x * blockDim.x + threadIdx.x;
    if (e >= E) return;
    int p = atomicAdd(&cur[ei[e]], 1);
    eidx[p] = e;
}

// ---------------- CSR gather: out[r][c] = b[c] + sum_e w_e * sup[src_e][c] ----------------
__global__ void k_gather(const int* __restrict__ rowstart, const int* __restrict__ eidx,
                         const int* __restrict__ ei, const float* __restrict__ ew,
                         const float* __restrict__ sup, const float* __restrict__ bias,
                         float* __restrict__ out, int E, int C)
{
    __shared__ int ssrc[128];
    __shared__ float swt[128];
    int r = blockIdx.x, c = threadIdx.x;     // C threads
    int s0 = rowstart[r], s1 = rowstart[r + 1];
    float acc = bias[c];
    for (int base = s0; base < s1; base += 128) {
        int len = min(128, s1 - base);
        __syncthreads();
        if (c < len) {
            int e = eidx[base + c];
            ssrc[c] = ei[E + e];
            swt[c]  = ew[e];
        }
        __syncthreads();
        for (int i = 0; i < len; i++)
            acc = fmaf(swt[i], sup[(size_t)ssrc[i] * C + c], acc);
    }
    out[(size_t)r * C + c] = acc;
}

// ---------------- support2 = relu(h) @ w_g2  (256 -> 128), 4 rows/block ----------------
__global__ void k_sup2(const float* __restrict__ h, const float* __restrict__ w,
                       float* __restrict__ sup)
{
    __shared__ float sh[4 * 256];
    int tid = threadIdx.x;           // 128
    int r0 = blockIdx.x * 4;
    #pragma unroll
    for (int i = tid; i < 1024; i += 128)
        sh[i] = fmaxf(h[(size_t)r0 * 256 + i], 0.f);
    __syncthreads();
    float a0 = 0, a1 = 0, a2 = 0, a3 = 0;
    #pragma unroll 4
    for (int k = 0; k < 256; k++) {
        float wv = w[k * 128 + tid];
        a0 = fmaf(sh[k], wv, a0);
        a1 = fmaf(sh[256 + k], wv, a1);
        a2 = fmaf(sh[512 + k], wv, a2);
        a3 = fmaf(sh[768 + k], wv, a3);
    }
    sup[(r0 + 0) * 128 + tid] = a0;
    sup[(r0 + 1) * 128 + tid] = a1;
    sup[(r0 + 2) * 128 + tid] = a2;
    sup[(r0 + 3) * 128 + tid] = a3;
}

// ---------------- proj + L2 normalize -> bf16 ----------------
__global__ void k_proj(const float* __restrict__ h,
                       const float* __restrict__ w1, const float* __restrict__ b1,
                       const float* __restrict__ w2, const float* __restrict__ b2,
                       __nv_bfloat16* __restrict__ zb)
{
    __shared__ float sh[128];
    __shared__ float t[64];
    __shared__ float red[128];
    int tid = threadIdx.x;           // 128
    int row = blockIdx.x;
    sh[tid] = h[row * 128 + tid];
    __syncthreads();
    if (tid < 64) {
        float a = b1[tid];
        #pragma unroll
        for (int k = 0; k < 128; k++)
            a = fmaf(sh[k], w1[k * 64 + tid], a);
        t[tid] = a > 0.f ? a : expm1f(a);
    }
    __syncthreads();
    float a = b2[tid];
    #pragma unroll
    for (int k = 0; k < 64; k++)
        a = fmaf(t[k], w2[k * 128 + tid], a);
    red[tid] = a * a;
    __syncthreads();
    for (int st = 64; st; st >>= 1) {
        if (tid < st) red[tid] += red[tid + st];
        __syncthreads();
    }
    float inv = 1.f / fmaxf(sqrtf(red[0]), 1e-12f);
    zb[row * 128 + tid] = __float2bfloat16(a * inv);
}

// ---------------- zero accumulators ----------------
__global__ void k_zero4(float* a, float* b, float* c, float* d)
{
    int i = blockIdx.x * blockDim.x + threadIdx.x;
    if (i < NN) { a[i] = 0.f; b[i] = 0.f; c[i] = 0.f; d[i] = 0.f; }
}

// ---------------- bf16 HMMA pairwise exp row-sums ----------------
// 4 jobs, rowsum-only:
//  job0: Z1 Z1^T -> rs11 (+d11)   job1: Z2 Z2^T -> rs22 (+d22)
//  job2: Z1 Z2^T -> rs12 (+d12)   job3: Z2 Z1^T -> cs12
// Block: 128x128 tile, 256 threads = 8 warps (4M x 2N), warp tile 32x64.
// A,B bf16 K-major in padded smem (stride 136), ldmatrix + mma.m16n8k16.
#define LDS_PAIR 136
__global__ void __launch_bounds__(256) k_pair_mma(
    const __nv_bfloat16* __restrict__ Zb1, const __nv_bfloat16* __restrict__ Zb2,
    float* __restrict__ rs11, float* __restrict__ d11,
    float* __restrict__ rs22, float* __restrict__ d22,
    float* __restrict__ rs12, float* __restrict__ d12,
    float* __restrict__ cs12)
{
    extern __shared__ __nv_bfloat16 smp[];
    __nv_bfloat16* As = smp;                       // 128 x 136
    __nv_bfloat16* Bs = smp + 128 * LDS_PAIR;      // 128 x 136

    int tid = threadIdx.x, wid = tid >> 5, lane = tid & 31;
    int wm = wid >> 1, wn = wid & 1;               // warp grid 4x2
    int job = blockIdx.z, ti = blockIdx.y, tj = blockIdx.x;

    const __nv_bfloat16* A = (job == 1 || job == 3) ? Zb2 : Zb1;
    const __nv_bfloat16* B = (job == 0 || job == 3) ? Zb1 : Zb2;
    float* RS = (job == 0) ? rs11 : (job == 1) ? rs22 : (job == 2) ? rs12 : cs12;
    float* DG = (job == 0) ? d11 : (job == 1) ? d22 : d12;
    bool dtile = (ti == tj) && (job < 3);

    // load 128x128 bf16 tiles (uint4 = 8 bf16 per thread-iter)
    const __nv_bfloat16* Ap = A + (size_t)ti * 128 * 128;
    const __nv_bfloat16* Bp = B + (size_t)tj * 128 * 128;
    #pragma unroll
    for (int it = 0; it < 8; it++) {
        int idx = it * 256 + tid;
        int row = idx >> 4, col8 = (idx & 15) * 8;
        *(uint4*)(As + row * LDS_PAIR + col8) = *(const uint4*)(Ap + (size_t)row * 128 + col8);
        *(uint4*)(Bs + row * LDS_PAIR + col8) = *(const uint4*)(Bp + (size_t)row * 128 + col8);
    }
    __syncthreads();

    float acc[2][8][4];
    #pragma unroll
    for (int mt = 0; mt < 2; mt++)
        #pragma unroll
        for (int nt = 0; nt < 8; nt++)
            #pragma unroll
            for (int q = 0; q < 4; q++) acc[mt][nt][q] = 0.f;

    uint32_t a_base = smem_u32(As);
    uint32_t b_base = smem_u32(Bs);
    int lrow = lane & 15, lcol = (lane >> 4) * 8;

    #pragma unroll
    for (int ks = 0; ks < 8; ks++) {
        int k0 = ks * 16;
        uint32_t af[2][4];
        #pragma unroll
        for (int mt = 0; mt < 2; mt++) {
            uint32_t addr = a_base + ((wm * 32 + mt * 16 + lrow) * LDS_PAIR + k0 + lcol) * 2;
            ldsm_x4(af[mt][0], af[mt][1], af[mt][2], af[mt][3], addr);
        }
        uint32_t bf[8][2];
        #pragma unroll
        for (int p = 0; p < 4; p++) {
            uint32_t r0, r1, r2, r3;
            uint32_t addr = b_base + ((wn * 64 + p * 16 + lrow) * LDS_PAIR + k0 + lcol) * 2;
            ldsm_x4(r0, r1, r2, r3, addr);
            bf[2 * p][0] = r0; bf[2 * p][1] = r2;
            bf[2 * p + 1][0] = r1; bf[2 * p + 1][1] = r3;
        }
        #pragma unroll
        for (int mt = 0; mt < 2; mt++)
            #pragma unroll
            for (int nt = 0; nt < 8; nt++)
                mma16816(acc[mt][nt], af[mt][0], af[mt][1], af[mt][2], af[mt][3],
                         bf[nt][0], bf[nt][1]);
    }

    // epilogue: e = exp(2*s); per-row sums; diag capture
    int qp = lane & 3, qr = lane >> 2;
    float rsum[2][2] = {{0.f, 0.f}, {0.f, 0.f}};
    #pragma unroll
    for (int mt = 0; mt < 2; mt++) {
        #pragma unroll
        for (int nt = 0; nt < 8; nt++) {
            #pragma unroll
            for (int q = 0; q < 4; q++) {
                float e = __expf(2.0f * acc[mt][nt][q]);   // 1/TEMP = 2
                rsum[mt][q >> 1] += e;
                if (dtile) {
                    int col = wn * 64 + nt * 8 + qp * 2 + (q & 1);
                    int row = wm * 32 + mt * 16 + qr + (q >> 1) * 8;
                    if (col == row) DG[ti * 128 + row] = e;
                }
            }
        }
    }
    // reduce across the quad (lanes sharing rows, differing cols)
    #pragma unroll
    for (int mt = 0; mt < 2; mt++)
        #pragma unroll
        for (int h = 0; h < 2; h++) {
            float v = rsum[mt][h];
            v += __shfl_xor_sync(0xFFFFFFFF, v, 1);
            v += __shfl_xor_sync(0xFFFFFFFF, v, 2);
            rsum[mt][h] = v;
        }
    if (qp == 0) {
        #pragma unroll
        for (int mt = 0; mt < 2; mt++)
            #pragma unroll
            for (int h = 0; h < 2; h++) {
                int row = ti * 128 + wm * 32 + mt * 16 + qr + h * 8;
                atomicAdd(&RS[row], rsum[mt][h]);
            }
    }
}

// ---------------- final loss reduction ----------------
__global__ void k_loss(const float* __restrict__ rs11, const float* __restrict__ d11,
                       const float* __restrict__ rs22, const float* __restrict__ d22,
                       const float* __restrict__ rs12, const float* __restrict__ cs12,
                       const float* __restrict__ d12, float* __restrict__ out)
{
    __shared__ float red[256];
    int tid = threadIdx.x;
    float s = 0.f;
    for (int i = tid; i < NN; i += 256) {
        float ld = logf(d12[i]);
        float l1 = logf(rs11[i] + rs12[i] - d11[i]) - ld;
        float l2 = logf(rs22[i] + cs12[i] - d22[i]) - ld;
        s += 0.5f * (l1 + l2);
    }
    red[tid] = s;
    __syncthreads();
    for (int st = 128; st; st >>= 1) {
        if (tid < st) red[tid] += red[tid + st];
        __syncthreads();
    }
    if (tid == 0) out[0] = red[0] / (float)NN;
}

// ---------------- launch ----------------
extern "C" void kernel_launch(void* const* d_in, const int* in_sizes, int n_in,
                              void* d_out, int out_size)
{
    const float* feat[2] = {(const float*)d_in[0], (const float*)d_in[1]};
    const int*   ei[2]   = {(const int*)d_in[2], (const int*)d_in[4]};
    const float* ew[2]   = {(const float*)d_in[3], (const float*)d_in[5]};
    const float* w_l1a = (const float*)d_in[6];
    const float* b_l1a = (const float*)d_in[7];
    const float* w_l1b = (const float*)d_in[8];
    const float* b_l1b = (const float*)d_in[9];
    const float* w_g1  = (const float*)d_in[10];
    const float* b_g1  = (const float*)d_in[11];
    const float* w_g2  = (const float*)d_in[12];
    const float* b_g2  = (const float*)d_in[13];
    const float* w_fc1 = (const float*)d_in[14];
    const float* b_fc1 = (const float*)d_in[15];
    const float* w_fc2 = (const float*)d_in[16];
    const float* b_fc2 = (const float*)d_in[17];
    int E = in_sizes[3];

    float *X, *S1, *G1, *S2, *G2;
    __nv_bfloat16 *Zb1, *Zb2;
    float *rs11, *rs22, *rs12, *cs12, *d11, *d22, *d12;
    int *cnt, *cur, *rowstart, *eidx;
    cudaGetSymbolAddress((void**)&X,  g_X);
    cudaGetSymbolAddress((void**)&S1, g_S1);
    cudaGetSymbolAddress((void**)&G1, g_G1);
    cudaGetSymbolAddress((void**)&S2, g_S2);
    cudaGetSymbolAddress((void**)&G2, g_G2);
    cudaGetSymbolAddress((void**)&Zb1, g_Zb1);
    cudaGetSymbolAddress((void**)&Zb2, g_Zb2);
    cudaGetSymbolAddress((void**)&rs11, g_rs11);
    cudaGetSymbolAddress((void**)&rs22, g_rs22);
    cudaGetSymbolAddress((void**)&rs12, g_rs12);
    cudaGetSymbolAddress((void**)&cs12, g_cs12);
    cudaGetSymbolAddress((void**)&d11, g_d11);
    cudaGetSymbolAddress((void**)&d22, g_d22);
    cudaGetSymbolAddress((void**)&d12, g_d12);
    cudaGetSymbolAddress((void**)&cnt, g_cnt);
    cudaGetSymbolAddress((void**)&cur, g_cur);
    cudaGetSymbolAddress((void**)&rowstart, g_rowstart);
    cudaGetSymbolAddress((void**)&eidx, g_eidx);

    const int PAIR_SMEM = 2 * 128 * LDS_PAIR * 2;   // 69632
    cudaFuncSetAttribute(k_pair_mma, cudaFuncAttributeMaxDynamicSharedMemorySize, PAIR_SMEM);

    int eg = (E + 255) / 256;

    for (int v = 0; v < 2; v++) {
        __nv_bfloat16* Zv = v ? Zb2 : Zb1;
        int* rsv = rowstart + v * (NN + 1);
        int* exv = eidx + v * EMAX;

        // CSR build for graph v
        k_zcnt<<<NN / 256, 256>>>(cnt);
        k_hist<<<eg, 256>>>(ei[v], cnt, E);
        k_scan<<<1, 1024>>>(cnt, rsv, cur);
        k_fill<<<eg, 256>>>(ei[v], cur, exv, E);

        k_mlp   <<<NN / 4, 64>>>(feat[v], w_l1a, b_l1a, w_l1b, b_l1b, X);
        k_sup1  <<<NN, 256>>>(X, w_g1, S1);
        k_gather<<<NN, CHID>>>(rsv, exv, ei[v], ew[v], S1, b_g1, G1, E, CHID);
        k_sup2  <<<NN / 4, 128>>>(G1, w_g2, S2);
        k_gather<<<NN, CACT>>>(rsv, exv, ei[v], ew[v], S2, b_g2, G2, E, CACT);
        k_proj  <<<NN, 128>>>(G2, w_fc1, b_fc1, w_fc2, b_fc2, Zv);
    }

    k_zero4<<<NN / 256, 256>>>(rs11, rs22, rs12, cs12);

    dim3 gp(64, 64, 4);
    k_pair_mma<<<gp, 256, PAIR_SMEM>>>(Zb1, Zb2, rs11, d11, rs22, d22, rs12, d12, cs12);

    k_loss<<<1, 256>>>(rs11, d11, rs22, d22, rs12, cs12, d12, (float*)d_out);
}